// round 4
// baseline (speedup 1.0000x reference)
#include <cuda_runtime.h>
#include <cuda_bf16.h>
#include <math.h>

#define LMX 16384

// ---------------- scratch ----------------
__device__ float g_bufA[4*LMX*64];
__device__ float g_bufB[4*LMX*64];
__device__ float g_xz  [4*LMX*256];
__device__ float g_u   [4*LMX*128];
__device__ float g_dt  [4*LMX*128];
__device__ float g_bc  [4*LMX*32];
__device__ float g_yz  [4*LMX*128];
__device__ float g_hend [4*256*128*16];
__device__ float g_hinit[4*256*128*16];
__device__ float g_sdt  [4*256*128];
__device__ float g_featT[4*1024*64];
__device__ float g_guideT[4*LMX*64];
__device__ float g_F1[4*1024*256];
__device__ float g_G1[4*LMX*256];
__device__ float g_W1f[256*64];
__device__ float g_W1g[256*64];
__device__ float g_Wr[512];

// ---------------- encoder convs ----------------
__global__ void k_conv_hsi(const float* __restrict__ in, const float* __restrict__ w,
                           const float* __restrict__ bias, float* __restrict__ outp) {
    int idx = blockIdx.x * 256 + threadIdx.x;
    if (idx >= 4*64*1024) return;
    int x = idx & 31, y = (idx >> 5) & 31, co = (idx >> 10) & 63, b = idx >> 16;
    float acc = bias[co];
    for (int ci = 0; ci < 31; ci++) {
        #pragma unroll
        for (int ky = 0; ky < 3; ky++) {
            int yy = y + ky - 1; if (yy < 0 || yy >= 32) continue;
            #pragma unroll
            for (int kx = 0; kx < 3; kx++) {
                int xx = x + kx - 1; if (xx < 0 || xx >= 32) continue;
                acc += w[((co*31 + ci)*3 + ky)*3 + kx] * in[((b*31 + ci)*32 + yy)*32 + xx];
            }
        }
    }
    outp[idx] = fmaxf(acc, 0.f);
}

__global__ void k_conv_msi(const float* __restrict__ in, const float* __restrict__ w,
                           const float* __restrict__ bias, float* __restrict__ outp) {
    int idx = blockIdx.x * 256 + threadIdx.x;
    if (idx >= 4*64*16384) return;
    int x = idx & 127, y = (idx >> 7) & 127, co = (idx >> 14) & 63, b = idx >> 20;
    float acc = bias[co];
    #pragma unroll
    for (int ci = 0; ci < 4; ci++) {
        #pragma unroll
        for (int ky = 0; ky < 3; ky++) {
            int yy = y + ky - 1; if (yy < 0 || yy >= 128) continue;
            #pragma unroll
            for (int kx = 0; kx < 3; kx++) {
                int xx = x + kx - 1; if (xx < 0 || xx >= 128) continue;
                acc += w[((co*4 + ci)*3 + ky)*3 + kx] * in[((b*4 + ci)*128 + yy)*128 + xx];
            }
        }
    }
    outp[idx] = fmaxf(acc, 0.f);
}

// ---------------- matmul: transposed-weight smem, broadcast activations ----------------
// Y[r,o] = bias[o] + sum_k X[r,k] W[o,k].  256 threads.
template<int IN, int OUT, int RT>
__global__ void k_mm(const float* __restrict__ X, const float* __restrict__ Wg,
                     const float* __restrict__ bias, float* __restrict__ Y) {
    constexpr int nOG = OUT/4;
    constexpr int NRG = 256/nOG;
    constexpr int RB  = RT*NRG;
    constexpr int WST = OUT + 4;
    extern __shared__ float sm[];
    float* WsT = sm;              // IN * WST
    float* Xs  = sm + IN*WST;     // RB * IN
    int tid = threadIdx.x;
    for (int i = tid; i < OUT*IN/4; i += 256) {
        float4 v = ((const float4*)Wg)[i];
        int o = i/(IN/4), k4 = (i%(IN/4))*4;
        WsT[(k4+0)*WST+o] = v.x; WsT[(k4+1)*WST+o] = v.y;
        WsT[(k4+2)*WST+o] = v.z; WsT[(k4+3)*WST+o] = v.w;
    }
    size_t row0 = (size_t)blockIdx.x * RB;
    for (int i = tid; i < RB*IN/4; i += 256)
        ((float4*)Xs)[i] = ((const float4*)(X + row0*IN))[i];
    __syncthreads();
    int og = tid % nOG, rg = tid / nOG;
    float4 bv = bias ? *(const float4*)(bias + og*4) : make_float4(0.f,0.f,0.f,0.f);
    float4 acc[RT];
    #pragma unroll
    for (int r = 0; r < RT; r++) acc[r] = bv;
    #pragma unroll 2
    for (int k = 0; k < IN; k++) {
        float4 wv = *(const float4*)&WsT[k*WST + og*4];
        #pragma unroll
        for (int r = 0; r < RT; r++) {
            float a = Xs[(rg*RT + r)*IN + k];
            acc[r].x += wv.x*a; acc[r].y += wv.y*a;
            acc[r].z += wv.z*a; acc[r].w += wv.w*a;
        }
    }
    #pragma unroll
    for (int r = 0; r < RT; r++)
        *(float4*)&Y[(row0 + rg*RT + r)*OUT + og*4] = acc[r];
}

// ---------------- depthwise conv + silu + x-proj + dt (16 tokens/block) ----------------
__global__ void k_convproj(const float* __restrict__ xz, const float* __restrict__ convw,
        const float* __restrict__ convb, const float* __restrict__ Wxp,
        const float* __restrict__ Wdt, const float* __restrict__ bdt,
        float* __restrict__ u_out, float* __restrict__ dt_out, float* __restrict__ bc_out, int L) {
    __shared__ float Wxpt[128*40], us[16*128], xds[16*40], Wdts[512], bdts[128], cws[512], cbs[128];
    int tid = threadIdx.x;
    for (int i = tid; i < 1152; i += 256) {
        float4 v = ((const float4*)Wxp)[i];
        int o = i >> 5, k4 = (i & 31)*4;
        Wxpt[(k4+0)*40+o] = v.x; Wxpt[(k4+1)*40+o] = v.y;
        Wxpt[(k4+2)*40+o] = v.z; Wxpt[(k4+3)*40+o] = v.w;
    }
    for (int i = tid; i < 512; i += 256) { Wdts[i] = Wdt[i]; cws[i] = convw[i]; }
    if (tid < 128) { bdts[tid] = bdt[tid]; cbs[tid] = convb[tid]; }
    __syncthreads();
    int g0 = blockIdx.x * 16;
    for (int i = tid; i < 2048; i += 256) {
        int tt = i >> 7, d = i & 127;
        int g = g0 + tt, t = g % L;
        float acc = cbs[d];
        #pragma unroll
        for (int j = 0; j < 4; j++)
            if (t - 3 + j >= 0) acc += cws[d*4+j] * xz[(size_t)(g-3+j)*256 + d];
        float uu = acc / (1.f + __expf(-acc));
        us[i] = uu;
        u_out[(size_t)g*128 + d] = uu;
    }
    __syncthreads();
    if (tid < 144) {   // 8 tt-pairs x 18 o-pairs, 2x2 outputs each
        int tp = tid / 18, op = tid % 18;
        int t0 = tp*2, o0 = op*2;
        float a00 = 0.f, a01 = 0.f, a10 = 0.f, a11 = 0.f;
        const float* u0p = &us[t0*128];
        const float* u1p = &us[(t0+1)*128];
        #pragma unroll 4
        for (int k = 0; k < 128; k++) {
            float u0 = u0p[k], u1 = u1p[k];
            float w0 = Wxpt[k*40 + o0], w1 = Wxpt[k*40 + o0 + 1];
            a00 += u0*w0; a01 += u0*w1; a10 += u1*w0; a11 += u1*w1;
        }
        xds[t0*40 + o0] = a00;     xds[t0*40 + o0 + 1] = a01;
        xds[(t0+1)*40 + o0] = a10; xds[(t0+1)*40 + o0 + 1] = a11;
    }
    __syncthreads();
    for (int i = tid; i < 512; i += 256) {  // bc out (o=4..35)
        int tt = i >> 5, o = (i & 31) + 4;
        bc_out[(size_t)(g0+tt)*32 + (i & 31)] = xds[tt*40 + o];
    }
    for (int i = tid; i < 2048; i += 256) {
        int tt = i >> 7, d = i & 127;
        float dtp = bdts[d];
        #pragma unroll
        for (int r = 0; r < 4; r++) dtp += xds[tt*40+r] * Wdts[d*4+r];
        float dtv = (dtp > 20.f) ? dtp : log1pf(__expf(dtp));
        dt_out[(size_t)(g0+tt)*128 + d] = dtv;
    }
}

// ---------------- scan helpers ----------------
__device__ __forceinline__ bool load_A(const float* Alog, int d, float* An) {
    #pragma unroll
    for (int n = 0; n < 16; n++) An[n] = -__expf(Alog[d*16 + n]);
    bool geom = true;
    #pragma unroll
    for (int n = 1; n < 16; n++)
        if (fabsf(An[n] - (float)(n+1)*An[0]) > 1e-4f*(float)(n+1)) geom = false;
    return geom;
}

template<int CH>
__global__ void k_scan1(const float* __restrict__ dt_a, const float* __restrict__ u_a,
                        const float* __restrict__ bc_a, const float* __restrict__ Alog,
                        float* __restrict__ hend, float* __restrict__ sdt_out, int NC) {
    extern __shared__ float smS[];
    float* dtS = smS;
    float* uS  = smS + CH*128;
    float* bcS = smS + CH*256;
    int b = blockIdx.x / NC, c = blockIdx.x % NC;
    int d = threadIdx.x;
    size_t base = (size_t)(b*NC + c)*CH;
    const float4* dg = (const float4*)(dt_a + base*128);
    const float4* ug = (const float4*)(u_a + base*128);
    const float4* bg = (const float4*)(bc_a + base*32);
    for (int i = d; i < CH*32; i += 128) { ((float4*)dtS)[i] = dg[i]; ((float4*)uS)[i] = ug[i]; }
    for (int i = d; i < CH*8;  i += 128) ((float4*)bcS)[i] = bg[i];
    __syncthreads();
    float An[16];
    bool geom = load_A(Alog, d, An);
    float h[16];
    #pragma unroll
    for (int n = 0; n < 16; n++) h[n] = 0.f;
    float s = 0.f;
    for (int tt = 0; tt < CH; tt++) {
        float dt = dtS[tt*128 + d];
        float du = dt * uS[tt*128 + d];
        s += dt;
        const float* Bv = &bcS[tt*32];
        if (geom) {
            float ep[16];
            ep[0] = __expf(dt * An[0]);
            #pragma unroll
            for (int n = 1; n < 16; n++) ep[n] = ep[(n-1)>>1]*ep[n>>1];
            #pragma unroll
            for (int n = 0; n < 16; n++) h[n] = ep[n]*h[n] + du*Bv[n];
        } else {
            #pragma unroll
            for (int n = 0; n < 16; n++) h[n] = __expf(dt*An[n])*h[n] + du*Bv[n];
        }
    }
    float* he = hend + ((size_t)(b*NC + c)*128 + d)*16;
    #pragma unroll
    for (int n = 0; n < 16; n++) he[n] = h[n];
    sdt_out[(b*NC + c)*128 + d] = s;
}

__global__ void k_carry(const float* __restrict__ hend, const float* __restrict__ sdt,
                        const float* __restrict__ Alog, float* __restrict__ hinit, int NC) {
    int b = blockIdx.x >> 1, half = blockIdx.x & 1;
    int tid = threadIdx.x;                    // 1024
    int d = half*64 + (tid >> 4), n = tid & 15;
    float An = -__expf(Alog[d*16 + n]);
    float h = 0.f;
    for (int c = 0; c < NC; c++) {
        size_t off = (size_t)(b*NC + c)*2048 + half*1024 + tid;
        hinit[off] = h;
        float s = sdt[(b*NC + c)*128 + d];
        h = __expf(s*An)*h + hend[off];
    }
}

template<int CH>
__global__ void k_scan2(const float* __restrict__ dt_a, const float* __restrict__ u_a,
                        const float* __restrict__ bc_a, const float* __restrict__ Alog,
                        const float* __restrict__ hinit, const float* __restrict__ xz,
                        const float* __restrict__ Dp, float* __restrict__ yz, int NC) {
    extern __shared__ float smS[];
    float* dtS = smS;
    float* uS  = smS + CH*128;
    float* bcS = smS + CH*256;
    int b = blockIdx.x / NC, c = blockIdx.x % NC;
    int d = threadIdx.x;
    size_t base = (size_t)(b*NC + c)*CH;
    const float4* dg = (const float4*)(dt_a + base*128);
    const float4* ug = (const float4*)(u_a + base*128);
    const float4* bg = (const float4*)(bc_a + base*32);
    for (int i = d; i < CH*32; i += 128) { ((float4*)dtS)[i] = dg[i]; ((float4*)uS)[i] = ug[i]; }
    for (int i = d; i < CH*8;  i += 128) ((float4*)bcS)[i] = bg[i];
    __syncthreads();
    float An[16];
    bool geom = load_A(Alog, d, An);
    float h[16];
    const float* hi = hinit + ((size_t)(b*NC + c)*128 + d)*16;
    #pragma unroll
    for (int n = 0; n < 16; n++) h[n] = hi[n];
    float dcoef = Dp[d];
    for (int tt = 0; tt < CH; tt++) {
        size_t row = base + tt;
        float dt = dtS[tt*128 + d];
        float u  = uS[tt*128 + d];
        float du = dt * u;
        float y = 0.f;
        const float* Bv = &bcS[tt*32];
        if (geom) {
            float ep[16];
            ep[0] = __expf(dt * An[0]);
            #pragma unroll
            for (int n = 1; n < 16; n++) ep[n] = ep[(n-1)>>1]*ep[n>>1];
            #pragma unroll
            for (int n = 0; n < 16; n++) {
                h[n] = ep[n]*h[n] + du*Bv[n]; y += h[n]*Bv[16 + n];
            }
        } else {
            #pragma unroll
            for (int n = 0; n < 16; n++) {
                h[n] = __expf(dt*An[n])*h[n] + du*Bv[n]; y += h[n]*Bv[16 + n];
            }
        }
        float ys = y + u*dcoef;
        float z = xz[row*256 + 128 + d];
        float sz = z / (1.f + __expf(-z));
        yz[row*128 + d] = ys * sz;
    }
}

// ---------------- tiled transpose (B,64,P) -> (B*P,64) ----------------
__global__ void k_transp(const float* __restrict__ src, float* __restrict__ dst, int P) {
    __shared__ float t[32][33];
    int p0 = blockIdx.x * 32, c0 = blockIdx.y * 32, b = blockIdx.z;
    int tx = threadIdx.x, ty = threadIdx.y;
    #pragma unroll
    for (int i = ty; i < 32; i += 8)
        t[i][tx] = src[((size_t)b*64 + c0 + i)*P + p0 + tx];
    __syncthreads();
    #pragma unroll
    for (int i = ty; i < 32; i += 8)
        dst[((size_t)b*P + p0 + i)*64 + c0 + tx] = t[tx][i];
}

// ---------------- pack W1 ----------------
__global__ void k_pack(const float* __restrict__ W1, float* __restrict__ W1f,
                       float* __restrict__ W1g, float* __restrict__ Wr) {
    int o = threadIdx.x;
    for (int c = 0; c < 64; c++) {
        W1f[o*64 + c] = W1[o*130 + c];
        W1g[o*64 + c] = W1[o*130 + 64 + c];
    }
    Wr[o*2]     = W1[o*130 + 128];
    Wr[o*2 + 1] = W1[o*130 + 129];
}

// ---------------- fused MLP tail v2 ----------------
// smem floats: W2T [k*132+j] 33792 | W3T [k*36+c] 4608 | h1T [k*68+inst] 17408
//              (h2 [inst*132+j] 8448 and prs [inst*36+c] 2304 alias h1T) | ps 192
#define TO_W2 0
#define TO_W3 33792
#define TO_H1 38400
#define TO_H2 38400
#define TO_PR (38400 + 8448)
#define TO_PS 55808
#define TO_TOT 56000

__global__ void k_tail(const float* __restrict__ F1, const float* __restrict__ G1,
                       const float* __restrict__ Wr_g, const float* __restrict__ b2g,
                       const float* __restrict__ W2g, const float* __restrict__ W3g,
                       const float* __restrict__ b3g, float* __restrict__ outp) {
    extern __shared__ float sm[];
    float* W2T = sm + TO_W2;
    float* W3T = sm + TO_W3;
    float* h1T = sm + TO_H1;
    float* h2  = sm + TO_H2;
    float* prs = sm + TO_PR;
    int*   frowS = (int*)(sm + TO_PS);
    float* relYS = sm + TO_PS + 64;
    float* relXS = sm + TO_PS + 128;
    int tid = threadIdx.x;
    for (int i = tid; i < 8192; i += 256) {          // W2 (128x256) -> W2T[k][j]
        float4 v = ((const float4*)W2g)[i];
        int j = i >> 6, k4 = (i & 63)*4;
        W2T[(k4+0)*132+j] = v.x; W2T[(k4+1)*132+j] = v.y;
        W2T[(k4+2)*132+j] = v.z; W2T[(k4+3)*132+j] = v.w;
    }
    for (int i = tid; i < 1024; i += 256) {          // W3 (32x128) -> W3T[k][c]
        float4 v = ((const float4*)W3g)[i];
        int c = i >> 5, k4 = (i & 31)*4;
        W3T[(k4+0)*36+c] = v.x; W3T[(k4+1)*36+c] = v.y;
        W3T[(k4+2)*36+c] = v.z; W3T[(k4+3)*36+c] = v.w;
    }
    float w0 = Wr_g[tid*2], w1 = Wr_g[tid*2 + 1];
    int jg = tid & 31, ig = tid >> 5;
    int j0 = jg*4, i0 = ig*8;
    float4 b2v = *(const float4*)(b2g + j0);
    float b3c = b3g[jg];
    __syncthreads();

    for (int pp = 0; pp < 4; pp++) {
        int pixA = blockIdx.x*64 + pp*16;
        if (tid < 64) {
            int pl = tid >> 2, s = tid & 3;
            int pix = pixA + pl;
            int yy = (pix >> 7) & 127, xx = pix & 127, bb = pix >> 14;
            float sy = (s & 2) ? 0.5f : -0.5f;
            float sx = (s & 1) ? 0.5f : -0.5f;
            int iyr = __float2int_rn((float)(2*yy+1)*0.125f - 0.5f + sy);
            int ixr = __float2int_rn((float)(2*xx+1)*0.125f - 0.5f + sx);
            if (iyr >= 0 && iyr < 32 && ixr >= 0 && ixr < 32) {
                frowS[tid] = bb*1024 + iyr*32 + ixr;
                relYS[tid] = (float)(2*yy+1)*0.25f - (float)(2*iyr+1);
                relXS[tid] = (float)(2*xx+1)*0.25f - (float)(2*ixr+1);
            } else {
                frowS[tid] = -1;
                relYS[tid] = (float)(2*yy+1)*0.25f - 32.f;
                relXS[tid] = (float)(2*xx+1)*0.25f - 32.f;
            }
        }
        __syncthreads();
        // ---- layer 1: thread = output o, writes h1T[o][inst] (float4 over 4 shifts)
        for (int pl = 0; pl < 16; pl++) {
            float g = G1[(size_t)(pixA + pl)*256 + tid];
            float4 vv;
            #pragma unroll
            for (int s = 0; s < 4; s++) {
                int inst = pl*4 + s;
                int fr = frowS[inst];
                float fv = (fr >= 0) ? F1[(size_t)fr*256 + tid] : 0.f;
                float v = g + fv + w0*relYS[inst] + w1*relXS[inst];
                (&vv.x)[s] = fmaxf(v, 0.f);
            }
            *(float4*)&h1T[tid*68 + pl*4] = vv;
        }
        __syncthreads();
        // ---- layer 2: 64 inst x 128 out; thread tile 8 inst x 4 out
        float4 acc[8];
        #pragma unroll
        for (int r = 0; r < 8; r++) acc[r] = b2v;
        #pragma unroll 2
        for (int k = 0; k < 256; k++) {
            float4 wv = *(const float4*)&W2T[k*132 + j0];
            const float* hp = &h1T[k*68 + i0];
            #pragma unroll
            for (int r = 0; r < 8; r++) {
                float a = hp[r];
                acc[r].x += wv.x*a; acc[r].y += wv.y*a;
                acc[r].z += wv.z*a; acc[r].w += wv.w*a;
            }
        }
        __syncthreads();   // h1T reads complete before h2 (aliased) is written
        #pragma unroll
        for (int r = 0; r < 8; r++) {
            float4 hv;
            hv.x = fmaxf(acc[r].x, 0.f); hv.y = fmaxf(acc[r].y, 0.f);
            hv.z = fmaxf(acc[r].z, 0.f); hv.w = fmaxf(acc[r].w, 0.f);
            *(float4*)&h2[(i0 + r)*132 + j0] = hv;
        }
        __syncthreads();
        // ---- layer 3: 64 inst x 32 out; thread tile 8 inst x 1 out (c = jg)
        {
            float a3[8];
            #pragma unroll
            for (int r = 0; r < 8; r++) a3[r] = b3c;
            #pragma unroll 2
            for (int k = 0; k < 128; k++) {
                float w = W3T[k*36 + jg];
                #pragma unroll
                for (int r = 0; r < 8; r++) a3[r] += w * h2[(i0 + r)*132 + k];
            }
            #pragma unroll
            for (int r = 0; r < 8; r++) prs[(i0 + r)*36 + jg] = a3[r];
        }
        __syncthreads();
        // ---- softmax over 4 shifts + combine + write
        for (int i = tid; i < 496; i += 256) {
            int pl = i / 31, c = i % 31;
            int base = pl*4;
            float l0 = prs[(base+0)*36 + 31];
            float l1 = prs[(base+1)*36 + 31];
            float l2 = prs[(base+2)*36 + 31];
            float l3 = prs[(base+3)*36 + 31];
            float m = fmaxf(fmaxf(l0, l1), fmaxf(l2, l3));
            float e0 = __expf(l0 - m), e1 = __expf(l1 - m);
            float e2 = __expf(l2 - m), e3 = __expf(l3 - m);
            float inv = 1.f / (e0 + e1 + e2 + e3);
            float v = (prs[(base+0)*36 + c]*e0 + prs[(base+1)*36 + c]*e1
                     + prs[(base+2)*36 + c]*e2 + prs[(base+3)*36 + c]*e3) * inv;
            int pix = pixA + pl;
            int bb = pix >> 14, yy = (pix >> 7) & 127, xx = pix & 127;
            outp[((size_t)bb*31 + c)*16384 + yy*128 + xx] = v;
        }
        __syncthreads();
    }
}

// ---------------- host ----------------
#define SMM_A ((64*260 + 32*64)*4)      // k_mm<64,256,8>
#define SMM_B ((128*68 + 128*128)*4)    // k_mm<128,64,8>
#define SSC16 ((16*256 + 16*32)*4)
#define SSC64 ((64*256 + 64*32)*4)

static void run_mamba(int blk, int CH, const float* inbuf, float* outbuf, int L,
                      const float* Win, const float* convw, const float* convb,
                      const float* Wxp, const float* Wdt, const float* bdt,
                      const float* Alog, const float* Dp, const float* Wout,
                      float* p_xz, float* p_u, float* p_dt, float* p_bc, float* p_yz,
                      float* p_hend, float* p_hinit, float* p_sdt) {
    int BL = 4 * L;
    int NC = L / CH;
    k_mm<64,256,8><<<BL/32, 256, SMM_A>>>(inbuf, Win + blk*16384, nullptr, p_xz);
    k_convproj<<<BL/16, 256>>>(p_xz, convw + blk*512, convb + blk*128, Wxp + blk*4608,
                               Wdt + blk*512, bdt + blk*128, p_u, p_dt, p_bc, L);
    if (CH == 16) {
        k_scan1<16><<<4*NC, 128, SSC16>>>(p_dt, p_u, p_bc, Alog + blk*2048, p_hend, p_sdt, NC);
        k_carry<<<8, 1024>>>(p_hend, p_sdt, Alog + blk*2048, p_hinit, NC);
        k_scan2<16><<<4*NC, 128, SSC16>>>(p_dt, p_u, p_bc, Alog + blk*2048, p_hinit, p_xz,
                                          Dp + blk*128, p_yz, NC);
    } else {
        k_scan1<64><<<4*NC, 128, SSC64>>>(p_dt, p_u, p_bc, Alog + blk*2048, p_hend, p_sdt, NC);
        k_carry<<<8, 1024>>>(p_hend, p_sdt, Alog + blk*2048, p_hinit, NC);
        k_scan2<64><<<4*NC, 128, SSC64>>>(p_dt, p_u, p_bc, Alog + blk*2048, p_hinit, p_xz,
                                          Dp + blk*128, p_yz, NC);
    }
    k_mm<128,64,8><<<BL/128, 256, SMM_B>>>(p_yz, Wout + blk*8192, nullptr, outbuf);
}

extern "C" void kernel_launch(void* const* d_in, const int* in_sizes, int n_in,
                              void* d_out, int out_size) {
    const float* hsi  = (const float*)d_in[0];
    const float* msi  = (const float*)d_in[1];
    const float* ehw  = (const float*)d_in[2];
    const float* ehb  = (const float*)d_in[3];
    const float* emw  = (const float*)d_in[4];
    const float* emb  = (const float*)d_in[5];
    const float* Win  = (const float*)d_in[6];
    const float* convw= (const float*)d_in[7];
    const float* convb= (const float*)d_in[8];
    const float* Wxp  = (const float*)d_in[9];
    const float* Wdt  = (const float*)d_in[10];
    const float* bdt  = (const float*)d_in[11];
    const float* Alog = (const float*)d_in[12];
    const float* Dp   = (const float*)d_in[13];
    const float* Wout = (const float*)d_in[14];
    const float* W1   = (const float*)d_in[15];
    const float* b1   = (const float*)d_in[16];
    const float* W2   = (const float*)d_in[17];
    const float* b2   = (const float*)d_in[18];
    const float* W3   = (const float*)d_in[19];
    const float* b3   = (const float*)d_in[20];
    float* outp = (float*)d_out;

    float *bufA, *bufB, *xz, *u, *dt, *bc, *yz, *hend, *hinit, *sdt;
    float *featT, *guideT, *F1, *G1, *W1f, *W1g, *Wr;
    cudaGetSymbolAddress((void**)&bufA, g_bufA);
    cudaGetSymbolAddress((void**)&bufB, g_bufB);
    cudaGetSymbolAddress((void**)&xz, g_xz);
    cudaGetSymbolAddress((void**)&u, g_u);
    cudaGetSymbolAddress((void**)&dt, g_dt);
    cudaGetSymbolAddress((void**)&bc, g_bc);
    cudaGetSymbolAddress((void**)&yz, g_yz);
    cudaGetSymbolAddress((void**)&hend, g_hend);
    cudaGetSymbolAddress((void**)&hinit, g_hinit);
    cudaGetSymbolAddress((void**)&sdt, g_sdt);
    cudaGetSymbolAddress((void**)&featT, g_featT);
    cudaGetSymbolAddress((void**)&guideT, g_guideT);
    cudaGetSymbolAddress((void**)&F1, g_F1);
    cudaGetSymbolAddress((void**)&G1, g_G1);
    cudaGetSymbolAddress((void**)&W1f, g_W1f);
    cudaGetSymbolAddress((void**)&W1g, g_W1g);
    cudaGetSymbolAddress((void**)&Wr, g_Wr);

    cudaFuncSetAttribute(k_mm<64,256,8>, cudaFuncAttributeMaxDynamicSharedMemorySize, SMM_A);
    cudaFuncSetAttribute(k_mm<128,64,8>, cudaFuncAttributeMaxDynamicSharedMemorySize, SMM_B);
    cudaFuncSetAttribute(k_scan1<64>, cudaFuncAttributeMaxDynamicSharedMemorySize, SSC64);
    cudaFuncSetAttribute(k_scan2<64>, cudaFuncAttributeMaxDynamicSharedMemorySize, SSC64);
    cudaFuncSetAttribute(k_tail, cudaFuncAttributeMaxDynamicSharedMemorySize, TO_TOT*4);

    // ---- hsi chain (blocks 0,1) ----
    k_conv_hsi<<<1024, 256>>>(hsi, ehw, ehb, bufA);
    run_mamba(0, 16, bufA, bufB, 1024, Win, convw, convb, Wxp, Wdt, bdt, Alog, Dp, Wout,
              xz, u, dt, bc, yz, hend, hinit, sdt);
    run_mamba(1, 16, bufB, bufA, 1024, Win, convw, convb, Wxp, Wdt, bdt, Alog, Dp, Wout,
              xz, u, dt, bc, yz, hend, hinit, sdt);
    {
        dim3 g(1024/32, 2, 4), blkd(32, 8);
        k_transp<<<g, blkd>>>(bufA, featT, 1024);
    }

    // ---- msi chain (blocks 2,3) ----
    k_conv_msi<<<16384, 256>>>(msi, emw, emb, bufB);
    run_mamba(2, 64, bufB, bufA, 16384, Win, convw, convb, Wxp, Wdt, bdt, Alog, Dp, Wout,
              xz, u, dt, bc, yz, hend, hinit, sdt);
    run_mamba(3, 64, bufA, bufB, 16384, Win, convw, convb, Wxp, Wdt, bdt, Alog, Dp, Wout,
              xz, u, dt, bc, yz, hend, hinit, sdt);
    {
        dim3 g(16384/32, 2, 4), blkd(32, 8);
        k_transp<<<g, blkd>>>(bufB, guideT, 16384);
    }

    // ---- implicit decoder ----
    k_pack<<<1, 256>>>(W1, W1f, W1g, Wr);
    k_mm<64,256,8><<<4*1024/32, 256, SMM_A>>>(featT, W1f, nullptr, F1);
    k_mm<64,256,8><<<4*16384/32, 256, SMM_A>>>(guideT, W1g, b1, G1);
    k_tail<<<1024, 256, TO_TOT*4>>>(F1, G1, Wr, b2, W2, W3, b3, outp);
}

// round 6
// speedup vs baseline: 1.1166x; 1.1166x over previous
#include <cuda_runtime.h>
#include <cuda_bf16.h>
#include <math.h>

#define LMX 16384

// ---------------- scratch ----------------
__device__ float g_bufA[4*LMX*64];
__device__ float g_bufB[4*LMX*64];
__device__ float g_xz  [4*LMX*256];
__device__ float g_u   [4*LMX*128];
__device__ float g_dt  [4*LMX*128];
__device__ float g_bc  [4*LMX*32];
__device__ float g_yz  [4*LMX*128];
__device__ float g_hend [4*256*128*16];
__device__ float g_hinit[4*256*128*16];
__device__ float g_sdt  [4*256*128];
__device__ float g_featT[4*1024*64];
__device__ float g_guideT[4*LMX*64];
__device__ float g_F1[4*1024*256];
__device__ float g_G1[4*LMX*256];
// pre-transposed (k-major) weights
__device__ float g_WinT[4*16384];
__device__ float g_WoutT[4*8192];
__device__ float g_W1fT[16384];
__device__ float g_W1gT[16384];
__device__ float g_Wr[512];
__device__ float g_W2T[32768];
__device__ float g_W3T[4096];
__device__ float g_WxpT[4*4608];
__device__ float g_WdtT[4*512];

// ---------------- one-shot weight prep ----------------
__global__ void k_prep(const float* __restrict__ Win, const float* __restrict__ Wout,
                       const float* __restrict__ W1, const float* __restrict__ W2,
                       const float* __restrict__ W3, const float* __restrict__ Wxp,
                       const float* __restrict__ Wdt,
                       float* WinT, float* WoutT, float* W1fT, float* W1gT, float* Wr,
                       float* W2T, float* W3T, float* WxpT, float* WdtT) {
    int i = blockIdx.x*256 + threadIdx.x;
    if (i < 65536) { int blk=i>>14, r=i&16383, k=r>>8, o=r&255; WinT[i]=Win[blk*16384+o*64+k]; return; }
    i -= 65536;
    if (i < 32768) { int blk=i>>13, r=i&8191, k=r>>6, o=r&63; WoutT[i]=Wout[blk*8192+o*128+k]; return; }
    i -= 32768;
    if (i < 16384) { int k=i>>8, o=i&255; W1fT[i]=W1[o*130+k]; return; }
    i -= 16384;
    if (i < 16384) { int k=i>>8, o=i&255; W1gT[i]=W1[o*130+64+k]; return; }
    i -= 16384;
    if (i < 512)   { Wr[i]=W1[(i>>1)*130+128+(i&1)]; return; }
    i -= 512;
    if (i < 32768) { int k=i>>7, j=i&127; W2T[i]=W2[j*256+k]; return; }
    i -= 32768;
    if (i < 4096)  { int k=i>>5, c=i&31; W3T[i]=W3[c*128+k]; return; }
    i -= 4096;
    if (i < 18432) { int blk=i/4608, r=i%4608, k=r/36, o=r%36; WxpT[i]=Wxp[blk*4608+o*128+k]; return; }
    i -= 18432;
    if (i < 2048)  { int blk=i>>9, rr=i&511, r=rr>>7, d=rr&127; WdtT[i]=Wdt[blk*512+d*4+r]; return; }
}

// ---------------- encoder convs ----------------
__global__ void k_conv_hsi(const float* __restrict__ in, const float* __restrict__ w,
                           const float* __restrict__ bias, float* __restrict__ outp) {
    int idx = blockIdx.x * 256 + threadIdx.x;
    if (idx >= 4*64*1024) return;
    int x = idx & 31, y = (idx >> 5) & 31, co = (idx >> 10) & 63, b = idx >> 16;
    float acc = bias[co];
    for (int ci = 0; ci < 31; ci++) {
        #pragma unroll
        for (int ky = 0; ky < 3; ky++) {
            int yy = y + ky - 1; if (yy < 0 || yy >= 32) continue;
            #pragma unroll
            for (int kx = 0; kx < 3; kx++) {
                int xx = x + kx - 1; if (xx < 0 || xx >= 32) continue;
                acc += w[((co*31 + ci)*3 + ky)*3 + kx] * in[((b*31 + ci)*32 + yy)*32 + xx];
            }
        }
    }
    outp[idx] = fmaxf(acc, 0.f);
}

__global__ void k_conv_msi(const float* __restrict__ in, const float* __restrict__ w,
                           const float* __restrict__ bias, float* __restrict__ outp) {
    int idx = blockIdx.x * 256 + threadIdx.x;
    if (idx >= 4*64*16384) return;
    int x = idx & 127, y = (idx >> 7) & 127, co = (idx >> 14) & 63, b = idx >> 20;
    float acc = bias[co];
    #pragma unroll
    for (int ci = 0; ci < 4; ci++) {
        #pragma unroll
        for (int ky = 0; ky < 3; ky++) {
            int yy = y + ky - 1; if (yy < 0 || yy >= 128) continue;
            #pragma unroll
            for (int kx = 0; kx < 3; kx++) {
                int xx = x + kx - 1; if (xx < 0 || xx >= 128) continue;
                acc += w[((co*4 + ci)*3 + ky)*3 + kx] * in[((b*4 + ci)*128 + yy)*128 + xx];
            }
        }
    }
    outp[idx] = fmaxf(acc, 0.f);
}

// ---------------- matmul with pre-transposed k-major weights ----------------
template<int IN, int OUT, int RT>
__global__ void k_mmT(const float* __restrict__ X, const float* __restrict__ WT,
                      const float* __restrict__ bias, float* __restrict__ Y) {
    constexpr int nOG = OUT/4;
    constexpr int RB  = RT*(256/nOG);
    extern __shared__ float sm[];
    float* Ws = sm;               // IN*OUT, k-major
    float* Xs = sm + IN*OUT;      // RB*IN
    int tid = threadIdx.x;
    for (int i = tid; i < OUT*IN/4; i += 256) ((float4*)Ws)[i] = ((const float4*)WT)[i];
    size_t row0 = (size_t)blockIdx.x * RB;
    for (int i = tid; i < RB*IN/4; i += 256)
        ((float4*)Xs)[i] = ((const float4*)(X + row0*IN))[i];
    __syncthreads();
    int og = tid % nOG, rg = tid / nOG;
    float4 bv = bias ? *(const float4*)(bias + og*4) : make_float4(0.f,0.f,0.f,0.f);
    float4 acc[RT];
    #pragma unroll
    for (int r = 0; r < RT; r++) acc[r] = bv;
    #pragma unroll 2
    for (int k = 0; k < IN; k++) {
        float4 wv = *(const float4*)&Ws[k*OUT + og*4];
        #pragma unroll
        for (int r = 0; r < RT; r++) {
            float a = Xs[(rg*RT + r)*IN + k];
            acc[r].x += wv.x*a; acc[r].y += wv.y*a;
            acc[r].z += wv.z*a; acc[r].w += wv.w*a;
        }
    }
    #pragma unroll
    for (int r = 0; r < RT; r++)
        *(float4*)&Y[(row0 + rg*RT + r)*OUT + og*4] = acc[r];
}

// ---------------- depthwise conv + silu + x-proj + dt ----------------
__global__ void k_convproj(const float* __restrict__ xz, const float* __restrict__ convw,
        const float* __restrict__ convb, const float* __restrict__ WxpT,
        const float* __restrict__ WdtT, const float* __restrict__ bdt,
        float* __restrict__ u_out, float* __restrict__ dt_out, float* __restrict__ bc_out, int L) {
    __shared__ float Wxpt[128*36], us[16*128], xds[16*40], Wdts[512], bdts[128], cws[512], cbs[128];
    int tid = threadIdx.x;
    for (int i = tid; i < 4608; i += 256) Wxpt[i] = WxpT[i];
    for (int i = tid; i < 512; i += 256) { Wdts[i] = WdtT[i]; cws[i] = convw[i]; }
    if (tid < 128) { bdts[tid] = bdt[tid]; cbs[tid] = convb[tid]; }
    __syncthreads();
    int g0 = blockIdx.x * 16;
    for (int i = tid; i < 2048; i += 256) {
        int tt = i >> 7, d = i & 127;
        int g = g0 + tt, t = g % L;
        float acc = cbs[d];
        #pragma unroll
        for (int j = 0; j < 4; j++)
            if (t - 3 + j >= 0) acc += cws[d*4+j] * xz[(size_t)(g-3+j)*256 + d];
        float uu = acc / (1.f + __expf(-acc));
        us[i] = uu;
        u_out[(size_t)g*128 + d] = uu;
    }
    __syncthreads();
    if (tid < 144) {
        int tp = tid / 18, op = tid % 18;
        int t0 = tp*2, o0 = op*2;
        float a00 = 0.f, a01 = 0.f, a10 = 0.f, a11 = 0.f;
        const float* u0p = &us[t0*128];
        const float* u1p = &us[(t0+1)*128];
        #pragma unroll 4
        for (int k = 0; k < 128; k++) {
            float u0 = u0p[k], u1 = u1p[k];
            float w0 = Wxpt[k*36 + o0], w1 = Wxpt[k*36 + o0 + 1];
            a00 += u0*w0; a01 += u0*w1; a10 += u1*w0; a11 += u1*w1;
        }
        xds[t0*40 + o0] = a00;     xds[t0*40 + o0 + 1] = a01;
        xds[(t0+1)*40 + o0] = a10; xds[(t0+1)*40 + o0 + 1] = a11;
    }
    __syncthreads();
    for (int i = tid; i < 512; i += 256) {
        int tt = i >> 5;
        bc_out[(size_t)(g0+tt)*32 + (i & 31)] = xds[tt*40 + (i & 31) + 4];
    }
    for (int i = tid; i < 2048; i += 256) {
        int tt = i >> 7, d = i & 127;
        float dtp = bdts[d];
        #pragma unroll
        for (int r = 0; r < 4; r++) dtp += xds[tt*40+r] * Wdts[r*128+d];
        float dtv = (dtp > 20.f) ? dtp : log1pf(__expf(dtp));
        dt_out[(size_t)(g0+tt)*128 + d] = dtv;
    }
}

// ---------------- scan helpers ----------------
__device__ __forceinline__ bool load_A(const float* Alog, int d, float* An) {
    #pragma unroll
    for (int n = 0; n < 16; n++) An[n] = -__expf(Alog[d*16 + n]);
    bool geom = true;
    #pragma unroll
    for (int n = 1; n < 16; n++)
        if (fabsf(An[n] - (float)(n+1)*An[0]) > 1e-4f*(float)(n+1)) geom = false;
    return geom;
}

template<int CH>
__global__ void k_scan1(const float* __restrict__ dt_a, const float* __restrict__ u_a,
                        const float* __restrict__ bc_a, const float* __restrict__ Alog,
                        float* __restrict__ hend, float* __restrict__ sdt_out, int NC) {
    extern __shared__ float smS[];
    float* dtS = smS;
    float* uS  = smS + CH*128;
    float* bcS = smS + CH*256;
    int b = blockIdx.x / NC, c = blockIdx.x % NC;
    int d = threadIdx.x;
    size_t base = (size_t)(b*NC + c)*CH;
    const float4* dg = (const float4*)(dt_a + base*128);
    const float4* ug = (const float4*)(u_a + base*128);
    const float4* bg = (const float4*)(bc_a + base*32);
    for (int i = d; i < CH*32; i += 128) { ((float4*)dtS)[i] = dg[i]; ((float4*)uS)[i] = ug[i]; }
    for (int i = d; i < CH*8;  i += 128) ((float4*)bcS)[i] = bg[i];
    __syncthreads();
    float An[16];
    bool geom = load_A(Alog, d, An);
    float h[16];
    #pragma unroll
    for (int n = 0; n < 16; n++) h[n] = 0.f;
    float s = 0.f;
    for (int tt = 0; tt < CH; tt++) {
        float dt = dtS[tt*128 + d];
        float du = dt * uS[tt*128 + d];
        s += dt;
        const float* Bv = &bcS[tt*32];
        if (geom) {
            float ep[16];
            ep[0] = __expf(dt * An[0]);
            #pragma unroll
            for (int n = 1; n < 16; n++) ep[n] = ep[(n-1)>>1]*ep[n>>1];
            #pragma unroll
            for (int n = 0; n < 16; n++) h[n] = ep[n]*h[n] + du*Bv[n];
        } else {
            #pragma unroll
            for (int n = 0; n < 16; n++) h[n] = __expf(dt*An[n])*h[n] + du*Bv[n];
        }
    }
    float* he = hend + ((size_t)(b*NC + c)*128 + d)*16;
    #pragma unroll
    for (int n = 0; n < 16; n++) he[n] = h[n];
    sdt_out[(b*NC + c)*128 + d] = s;
}

__global__ void k_carry(const float* __restrict__ hend, const float* __restrict__ sdt,
                        const float* __restrict__ Alog, float* __restrict__ hinit, int NC) {
    int b = blockIdx.x >> 1, half = blockIdx.x & 1;
    int tid = threadIdx.x;
    int d = half*64 + (tid >> 4), n = tid & 15;
    float An = -__expf(Alog[d*16 + n]);
    float h = 0.f;
    for (int c = 0; c < NC; c++) {
        size_t off = (size_t)(b*NC + c)*2048 + half*1024 + tid;
        hinit[off] = h;
        float s = sdt[(b*NC + c)*128 + d];
        h = __expf(s*An)*h + hend[off];
    }
}

template<int CH>
__global__ void k_scan2(const float* __restrict__ dt_a, const float* __restrict__ u_a,
                        const float* __restrict__ bc_a, const float* __restrict__ Alog,
                        const float* __restrict__ hinit, const float* __restrict__ xz,
                        const float* __restrict__ Dp, float* __restrict__ yz, int NC) {
    extern __shared__ float smS[];
    float* dtS = smS;
    float* uS  = smS + CH*128;
    float* bcS = smS + CH*256;
    int b = blockIdx.x / NC, c = blockIdx.x % NC;
    int d = threadIdx.x;
    size_t base = (size_t)(b*NC + c)*CH;
    const float4* dg = (const float4*)(dt_a + base*128);
    const float4* ug = (const float4*)(u_a + base*128);
    const float4* bg = (const float4*)(bc_a + base*32);
    for (int i = d; i < CH*32; i += 128) { ((float4*)dtS)[i] = dg[i]; ((float4*)uS)[i] = ug[i]; }
    for (int i = d; i < CH*8;  i += 128) ((float4*)bcS)[i] = bg[i];
    __syncthreads();
    float An[16];
    bool geom = load_A(Alog, d, An);
    float h[16];
    const float* hi = hinit + ((size_t)(b*NC + c)*128 + d)*16;
    #pragma unroll
    for (int n = 0; n < 16; n++) h[n] = hi[n];
    float dcoef = Dp[d];
    for (int tt = 0; tt < CH; tt++) {
        size_t row = base + tt;
        float dt = dtS[tt*128 + d];
        float u  = uS[tt*128 + d];
        float du = dt * u;
        float y = 0.f;
        const float* Bv = &bcS[tt*32];
        if (geom) {
            float ep[16];
            ep[0] = __expf(dt * An[0]);
            #pragma unroll
            for (int n = 1; n < 16; n++) ep[n] = ep[(n-1)>>1]*ep[n>>1];
            #pragma unroll
            for (int n = 0; n < 16; n++) {
                h[n] = ep[n]*h[n] + du*Bv[n]; y += h[n]*Bv[16 + n];
            }
        } else {
            #pragma unroll
            for (int n = 0; n < 16; n++) {
                h[n] = __expf(dt*An[n])*h[n] + du*Bv[n]; y += h[n]*Bv[16 + n];
            }
        }
        float ys = y + u*dcoef;
        float z = xz[row*256 + 128 + d];
        float sz = z / (1.f + __expf(-z));
        yz[row*128 + d] = ys * sz;
    }
}

// ---------------- tiled transpose (B,64,P) -> (B*P,64) ----------------
__global__ void k_transp(const float* __restrict__ src, float* __restrict__ dst, int P) {
    __shared__ float t[32][33];
    int p0 = blockIdx.x * 32, c0 = blockIdx.y * 32, b = blockIdx.z;
    int tx = threadIdx.x, ty = threadIdx.y;
    #pragma unroll
    for (int i = ty; i < 32; i += 8)
        t[i][tx] = src[((size_t)b*64 + c0 + i)*P + p0 + tx];
    __syncthreads();
    #pragma unroll
    for (int i = ty; i < 32; i += 8)
        dst[((size_t)b*P + p0 + i)*64 + c0 + tx] = t[tx][i];
}

// ---------------- fused MLP tail ----------------
// floats: sW2 [k*132+j] 33792 | sW3 [k*33+c] 4224 | h1T [k*68+inst] 17408 (h2/prs alias) | ps 192
#define TO_W3 33792
#define TO_H1 38016
#define TO_PR (38016 + 8448)
#define TO_PS 55424
#define TO_TOT 55616

__global__ void k_tail(const float* __restrict__ F1, const float* __restrict__ G1,
                       const float* __restrict__ Wr_g, const float* __restrict__ b2g,
                       const float* __restrict__ W2Tg, const float* __restrict__ W3Tg,
                       const float* __restrict__ b3g, float* __restrict__ outp) {
    extern __shared__ float sm[];
    float* sW2 = sm;
    float* sW3 = sm + TO_W3;
    float* h1T = sm + TO_H1;
    float* h2  = sm + TO_H1;
    float* prs = sm + TO_PR;
    int*   frowS = (int*)(sm + TO_PS);
    float* relYS = sm + TO_PS + 64;
    float* relXS = sm + TO_PS + 128;
    int tid = threadIdx.x;
    for (int i = tid; i < 32768; i += 256) { int k = i >> 7, j = i & 127; sW2[k*132 + j] = W2Tg[i]; }
    for (int i = tid; i < 4096;  i += 256) { int k = i >> 5, c = i & 31;  sW3[k*33 + c]  = W3Tg[i]; }
    float w0 = Wr_g[tid*2], w1 = Wr_g[tid*2 + 1];
    int jg = tid & 31, ig = tid >> 5;
    int j0 = jg*4, i0 = ig*8;
    float4 b2v = *(const float4*)(b2g + j0);
    float b3c = b3g[jg];
    __syncthreads();

    for (int pp = 0; pp < 4; pp++) {
        int pixA = blockIdx.x*64 + pp*16;
        if (tid < 64) {
            int pl = tid >> 2, s = tid & 3;
            int pix = pixA + pl;
            int yy = (pix >> 7) & 127, xx = pix & 127, bb = pix >> 14;
            float sy = (s & 2) ? 0.5f : -0.5f;
            float sx = (s & 1) ? 0.5f : -0.5f;
            int iyr = __float2int_rn((float)(2*yy+1)*0.125f - 0.5f + sy);
            int ixr = __float2int_rn((float)(2*xx+1)*0.125f - 0.5f + sx);
            if (iyr >= 0 && iyr < 32 && ixr >= 0 && ixr < 32) {
                frowS[tid] = bb*1024 + iyr*32 + ixr;
                relYS[tid] = (float)(2*yy+1)*0.25f - (float)(2*iyr+1);
                relXS[tid] = (float)(2*xx+1)*0.25f - (float)(2*ixr+1);
            } else {
                frowS[tid] = -1;
                relYS[tid] = (float)(2*yy+1)*0.25f - 32.f;
                relXS[tid] = (float)(2*xx+1)*0.25f - 32.f;
            }
        }
        __syncthreads();
        // layer 1: thread = output o; h1T[o][inst], float4 over 4 shifts
        for (int pl = 0; pl < 16; pl++) {
            float g = G1[(size_t)(pixA + pl)*256 + tid];
            float4 vv;
            #pragma unroll
            for (int s = 0; s < 4; s++) {
                int inst = pl*4 + s;
                int fr = frowS[inst];
                float fv = (fr >= 0) ? F1[(size_t)fr*256 + tid] : 0.f;
                float v = g + fv + w0*relYS[inst] + w1*relXS[inst];
                (&vv.x)[s] = fmaxf(v, 0.f);
            }
            *(float4*)&h1T[tid*68 + pl*4] = vv;
        }
        __syncthreads();
        // layer 2: 64 inst x 128 out; thread tile 8 inst x 4 out
        float4 acc[8];
        #pragma unroll
        for (int r = 0; r < 8; r++) acc[r] = b2v;
        #pragma unroll 2
        for (int k = 0; k < 256; k++) {
            float4 wv = *(const float4*)&sW2[k*132 + j0];
            float ha[8];
            *(float4*)&ha[0] = *(const float4*)&h1T[k*68 + i0];
            *(float4*)&ha[4] = *(const float4*)&h1T[k*68 + i0 + 4];
            #pragma unroll
            for (int r = 0; r < 8; r++) {
                float a = ha[r];
                acc[r].x += wv.x*a; acc[r].y += wv.y*a;
                acc[r].z += wv.z*a; acc[r].w += wv.w*a;
            }
        }
        __syncthreads();
        #pragma unroll
        for (int r = 0; r < 8; r++) {
            float4 hv;
            hv.x = fmaxf(acc[r].x, 0.f); hv.y = fmaxf(acc[r].y, 0.f);
            hv.z = fmaxf(acc[r].z, 0.f); hv.w = fmaxf(acc[r].w, 0.f);
            *(float4*)&h2[(i0 + r)*132 + j0] = hv;
        }
        __syncthreads();
        // layer 3: 64 inst x 32 out; thread tile 8 inst x 1 out
        {
            float a3[8];
            #pragma unroll
            for (int r = 0; r < 8; r++) a3[r] = b3c;
            #pragma unroll 2
            for (int k = 0; k < 128; k++) {
                float w = sW3[k*33 + jg];
                #pragma unroll
                for (int r = 0; r < 8; r++) a3[r] += w * h2[(i0 + r)*132 + k];
            }
            #pragma unroll
            for (int r = 0; r < 8; r++) prs[(i0 + r)*36 + jg] = a3[r];
        }
        __syncthreads();
        // softmax over 4 shifts + combine
        for (int i = tid; i < 496; i += 256) {
            int pl = i / 31, c = i % 31;
            int base = pl*4;
            float l0 = prs[(base+0)*36 + 31];
            float l1 = prs[(base+1)*36 + 31];
            float l2 = prs[(base+2)*36 + 31];
            float l3 = prs[(base+3)*36 + 31];
            float m = fmaxf(fmaxf(l0, l1), fmaxf(l2, l3));
            float e0 = __expf(l0 - m), e1 = __expf(l1 - m);
            float e2 = __expf(l2 - m), e3 = __expf(l3 - m);
            float inv = 1.f / (e0 + e1 + e2 + e3);
            float v = (prs[(base+0)*36 + c]*e0 + prs[(base+1)*36 + c]*e1
                     + prs[(base+2)*36 + c]*e2 + prs[(base+3)*36 + c]*e3) * inv;
            int pix = pixA + pl;
            int bb = pix >> 14, yy = (pix >> 7) & 127, xx = pix & 127;
            outp[((size_t)bb*31 + c)*16384 + yy*128 + xx] = v;
        }
        __syncthreads();
    }
}

// ---------------- host ----------------
#define SMM_A ((64*256 + 32*64)*4)
#define SMM_B ((128*64 + 128*128)*4)
#define SSC16 ((16*256 + 16*32)*4)
#define SSC64 ((64*256 + 64*32)*4)

static void run_mamba(int blk, int CH, const float* inbuf, float* outbuf, int L,
                      const float* WinT, const float* convw, const float* convb,
                      const float* WxpT, const float* WdtT, const float* bdt,
                      const float* Alog, const float* Dp, const float* WoutT,
                      float* p_xz, float* p_u, float* p_dt, float* p_bc, float* p_yz,
                      float* p_hend, float* p_hinit, float* p_sdt) {
    int BL = 4 * L;
    int NC = L / CH;
    k_mmT<64,256,8><<<BL/32, 256, SMM_A>>>(inbuf, WinT + blk*16384, nullptr, p_xz);
    k_convproj<<<BL/16, 256>>>(p_xz, convw + blk*512, convb + blk*128, WxpT + blk*4608,
                               WdtT + blk*512, bdt + blk*128, p_u, p_dt, p_bc, L);
    if (CH == 16) {
        k_scan1<16><<<4*NC, 128, SSC16>>>(p_dt, p_u, p_bc, Alog + blk*2048, p_hend, p_sdt, NC);
        k_carry<<<8, 1024>>>(p_hend, p_sdt, Alog + blk*2048, p_hinit, NC);
        k_scan2<16><<<4*NC, 128, SSC16>>>(p_dt, p_u, p_bc, Alog + blk*2048, p_hinit, p_xz,
                                          Dp + blk*128, p_yz, NC);
    } else {
        k_scan1<64><<<4*NC, 128, SSC64>>>(p_dt, p_u, p_bc, Alog + blk*2048, p_hend, p_sdt, NC);
        k_carry<<<8, 1024>>>(p_hend, p_sdt, Alog + blk*2048, p_hinit, NC);
        k_scan2<64><<<4*NC, 128, SSC64>>>(p_dt, p_u, p_bc, Alog + blk*2048, p_hinit, p_xz,
                                          Dp + blk*128, p_yz, NC);
    }
    k_mmT<128,64,8><<<BL/128, 256, SMM_B>>>(p_yz, WoutT + blk*8192, nullptr, outbuf);
}

extern "C" void kernel_launch(void* const* d_in, const int* in_sizes, int n_in,
                              void* d_out, int out_size) {
    const float* hsi  = (const float*)d_in[0];
    const float* msi  = (const float*)d_in[1];
    const float* ehw  = (const float*)d_in[2];
    const float* ehb  = (const float*)d_in[3];
    const float* emw  = (const float*)d_in[4];
    const float* emb  = (const float*)d_in[5];
    const float* Win  = (const float*)d_in[6];
    const float* convw= (const float*)d_in[7];
    const float* convb= (const float*)d_in[8];
    const float* Wxp  = (const float*)d_in[9];
    const float* Wdt  = (const float*)d_in[10];
    const float* bdt  = (const float*)d_in[11];
    const float* Alog = (const float*)d_in[12];
    const float* Dp   = (const float*)d_in[13];
    const float* Wout = (const float*)d_in[14];
    const float* W1   = (const float*)d_in[15];
    const float* b1   = (const float*)d_in[16];
    const float* W2   = (const float*)d_in[17];
    const float* b2   = (const float*)d_in[18];
    const float* W3   = (const float*)d_in[19];
    const float* b3   = (const float*)d_in[20];
    float* outp = (float*)d_out;

    float *bufA, *bufB, *xz, *u, *dt, *bc, *yz, *hend, *hinit, *sdt, *featT, *guideT, *F1, *G1;
    float *WinT, *WoutT, *W1fT, *W1gT, *Wr, *W2T, *W3T, *WxpT, *WdtT;
    cudaGetSymbolAddress((void**)&bufA, g_bufA);
    cudaGetSymbolAddress((void**)&bufB, g_bufB);
    cudaGetSymbolAddress((void**)&xz, g_xz);
    cudaGetSymbolAddress((void**)&u, g_u);
    cudaGetSymbolAddress((void**)&dt, g_dt);
    cudaGetSymbolAddress((void**)&bc, g_bc);
    cudaGetSymbolAddress((void**)&yz, g_yz);
    cudaGetSymbolAddress((void**)&hend, g_hend);
    cudaGetSymbolAddress((void**)&hinit, g_hinit);
    cudaGetSymbolAddress((void**)&sdt, g_sdt);
    cudaGetSymbolAddress((void**)&featT, g_featT);
    cudaGetSymbolAddress((void**)&guideT, g_guideT);
    cudaGetSymbolAddress((void**)&F1, g_F1);
    cudaGetSymbolAddress((void**)&G1, g_G1);
    cudaGetSymbolAddress((void**)&WinT, g_WinT);
    cudaGetSymbolAddress((void**)&WoutT, g_WoutT);
    cudaGetSymbolAddress((void**)&W1fT, g_W1fT);
    cudaGetSymbolAddress((void**)&W1gT, g_W1gT);
    cudaGetSymbolAddress((void**)&Wr, g_Wr);
    cudaGetSymbolAddress((void**)&W2T, g_W2T);
    cudaGetSymbolAddress((void**)&W3T, g_W3T);
    cudaGetSymbolAddress((void**)&WxpT, g_WxpT);
    cudaGetSymbolAddress((void**)&WdtT, g_WdtT);

    cudaFuncSetAttribute(k_mmT<64,256,8>, cudaFuncAttributeMaxDynamicSharedMemorySize, SMM_A);
    cudaFuncSetAttribute(k_mmT<128,64,8>, cudaFuncAttributeMaxDynamicSharedMemorySize, SMM_B);
    cudaFuncSetAttribute(k_scan1<64>, cudaFuncAttributeMaxDynamicSharedMemorySize, SSC64);
    cudaFuncSetAttribute(k_scan2<64>, cudaFuncAttributeMaxDynamicSharedMemorySize, SSC64);
    cudaFuncSetAttribute(k_tail, cudaFuncAttributeMaxDynamicSharedMemorySize, TO_TOT*4);

    k_prep<<<739, 256>>>(Win, Wout, W1, W2, W3, Wxp, Wdt,
                         WinT, WoutT, W1fT, W1gT, Wr, W2T, W3T, WxpT, WdtT);

    k_conv_hsi<<<1024, 256>>>(hsi, ehw, ehb, bufA);
    run_mamba(0, 16, bufA, bufB, 1024, WinT, convw, convb, WxpT, WdtT, bdt, Alog, Dp, WoutT,
              xz, u, dt, bc, yz, hend, hinit, sdt);
    run_mamba(1, 16, bufB, bufA, 1024, WinT, convw, convb, WxpT, WdtT, bdt, Alog, Dp, WoutT,
              xz, u, dt, bc, yz, hend, hinit, sdt);
    { dim3 g(1024/32, 2, 4), blkd(32, 8); k_transp<<<g, blkd>>>(bufA, featT, 1024); }

    k_conv_msi<<<16384, 256>>>(msi, emw, emb, bufB);
    run_mamba(2, 64, bufB, bufA, 16384, WinT, convw, convb, WxpT, WdtT, bdt, Alog, Dp, WoutT,
              xz, u, dt, bc, yz, hend, hinit, sdt);
    run_mamba(3, 64, bufA, bufB, 16384, WinT, convw, convb, WxpT, WdtT, bdt, Alog, Dp, WoutT,
              xz, u, dt, bc, yz, hend, hinit, sdt);
    { dim3 g(16384/32, 2, 4), blkd(32, 8); k_transp<<<g, blkd>>>(bufB, guideT, 16384); }

    k_mmT<64,256,8><<<4*1024/32, 256, SMM_A>>>(featT, W1fT, nullptr, F1);
    k_mmT<64,256,8><<<4*16384/32, 256, SMM_A>>>(guideT, W1gT, b1, G1);
    k_tail<<<1024, 256, TO_TOT*4>>>(F1, G1, Wr, b2, W2T, W3T, b3, outp);
}